// round 14
// baseline (speedup 1.0000x reference)
#include <cuda_runtime.h>

#define Nn 2048
#define SEG 32
#define RPB 10                    /* rows per block */
#define THREADS (RPB*2*32)        /* 640: 2 warps per row */
#define PITCH (Nn + Nn/32)        /* 2112 floats, >>5 swizzle pitch */
/* smem: cs 2*PITCH | w PITCH | Bseg 64 | buf RPB*PITCH | ptot 2*RPB */
#define SMEM_FLOATS (2*PITCH + PITCH + 64 + RPB*PITCH + 2*RPB)
#define SMEM_BYTES (SMEM_FLOATS*4)   /* 110,160 B -> 2 blocks/SM (40 warps) */

#define NAMED_BAR(id) asm volatile("bar.sync %0, %1;" :: "r"(id), "r"(64) : "memory")

__device__ float2 g_cs[Nn];
__device__ float  g_w[Nn];
__device__ float  g_Bseg[Nn/SEG];

__global__ void cs_kernel(const float* __restrict__ angles) {
    int i = blockIdx.x * blockDim.x + threadIdx.x;
    if (i < Nn) {
        float a = angles[i];
        float2 v; v.x = cosf(a); v.y = sinf(a);
        g_cs[i] = v;
    }
}

// Per 32-aligned k-block m (k in [32m, 32m+32)):
//   w[k]    = c_k * prod_{k'=32m}^{k-1} (-s_{k'})   (coeff of x'[k] at segment exit)
//   Bseg[m] = prod over whole block of (-s)
// Segment g processes k-block m = 63 - g (k descending from 2047-32g).
__global__ void wseg_kernel() {
    int m = threadIdx.x;              // 0..63
    float prod = 1.f;
    for (int k = 32*m; k < 32*m + 32; k++) {
        float2 csv = g_cs[k];
        g_w[k] = csv.x * prod;
        prod = -csv.y * prod;
    }
    g_Bseg[m] = prod;
}

// y = R x per row, R = G_0..G_{n-1} applied k = n-1 .. 0.
// Carry: u_{t+1} = c_k*x'[k] - s_k*u_t (k = n-1-t), u_0 = x[0],
// x'[0] = s_{n-1}x[n-1] + c_{n-1}x[0].  Outputs y[k+1] = s_k*x'[k] + c_k*u_t
// (t>=1), y[0] = u_n.  Row split across 2 warps (h=0,1), 64 segments of 32.
// Pass A = dot product with precomputed w (no serial chain); segment B from
// Bseg table; warp scan of affine (A,B); pass B replays with c,s for outputs.
__global__ void __launch_bounds__(THREADS, 2)
givens_kernel(const float* __restrict__ x, float* __restrict__ y, int n_rows) {
    extern __shared__ float smem[];
    float2* cs     = (float2*)smem;                       // PITCH float2
    float*  wsm    = smem + 2*PITCH;                      // PITCH floats
    float*  Bsm    = smem + 3*PITCH;                      // 64 floats
    float*  bufall = smem + 3*PITCH + 64;                 // RPB row buffers
    float*  ptot   = smem + 3*PITCH + 64 + RPB*PITCH;     // per-row (A,B) of h0

    int tid  = threadIdx.x;
    int lane = tid & 31;
    int w    = tid >> 5;
    int r    = w >> 1;          // row within block
    int h    = w & 1;           // row half

    // Stage tables, swizzled addr(k) = k + (k>>5)
    for (int i = tid; i < Nn; i += THREADS) {
        cs [i + (i >> 5)] = g_cs[i];
        wsm[i + (i >> 5)] = g_w[i];
    }
    if (tid < Nn/SEG) Bsm[tid] = g_Bseg[tid];

    float* buf = bufall + r * PITCH;
    long row = (long)blockIdx.x * RPB + r;
    int active = row < n_rows;
    const float* xr = x + row * (long)Nn;

    // Stage this half of the row, coalesced float4
    if (active) {
        for (int i = h*1024 + lane*4; i < (h+1)*1024; i += 128) {
            float4 v = *reinterpret_cast<const float4*>(xr + i);
            int a = i + (i >> 5);         // i%4==0 -> 4 contiguous slots
            buf[a]   = v.x; buf[a+1] = v.y;
            buf[a+2] = v.z; buf[a+3] = v.w;
        }
    }
    __syncthreads();                      // tables + both halves visible
    if (!active) return;                  // whole pair exits uniformly

    float u0 = buf[0];                    // x[0] (addr(0) == 0), all pair lanes
    NAMED_BAR(r + 1);                     // reads of buf[0] before overwrite
    if (h == 0 && lane == 0) {
        float2 cN = cs[2047 + (2047 >> 5)];
        float  xN = buf[2047 + (2047 >> 5)];
        buf[0] = cN.y * xN + cN.x * u0;   // x'[0]
    }
    NAMED_BAR(r + 1);

    int g     = h*32 + lane;              // global segment 0..63 (t order)
    int kbase = Nn - 1 - g*SEG;
    int base  = kbase + (kbase >> 5);     // swizzle offset constant in segment

    // ---- Pass A: dot product  A = sum w*xv  (chain-free, 2 accumulators) ----
    float A0 = 0.f, A1 = 0.f;
    #pragma unroll 8
    for (int p = 0; p < SEG; p += 2) {
        A0 = fmaf(wsm[base - p],     buf[base - p],     A0);
        A1 = fmaf(wsm[base - p - 1], buf[base - p - 1], A1);
    }
    float A  = A0 + A1;
    float Bb = Bsm[63 - g];               // segment g -> k-block 63-g

    // ---- Intra-warp inclusive scan of affine maps ----
    #pragma unroll
    for (int d = 1; d < 32; d <<= 1) {
        float Ap = __shfl_up_sync(0xffffffffu, A,  d);
        float Bp = __shfl_up_sync(0xffffffffu, Bb, d);
        if (lane >= d) { A = fmaf(Bb, Ap, A); Bb *= Bp; }
    }
    if (h == 0 && lane == 31) { ptot[2*r] = A; ptot[2*r + 1] = Bb; }
    NAMED_BAR(r + 1);

    // Entry carry: h1 pre-applies h0's total map to u0
    float v0 = u0;
    if (h == 1) v0 = fmaf(ptot[2*r + 1], u0, ptot[2*r]);
    float Ae = __shfl_up_sync(0xffffffffu, A,  1);
    float Be = __shfl_up_sync(0xffffffffu, Bb, 1);
    float u  = (lane == 0) ? v0 : fmaf(Be, v0, Ae);

    // ---- Pass B: replay, emit y[k+1] into freed slot k ----
    {   // peel p=0: segment g==0 (t=0) produces no output -> skip store,
        // leaving slot addr(2047) solely to the y[0] writer below.
        float2 c  = cs[base];
        float  xv = buf[base];
        if (g != 0) buf[base] = fmaf(c.x, u, c.y * xv);
        u = fmaf(-c.y, u, c.x * xv);
    }
    #pragma unroll 8
    for (int p = 1; p < SEG; p++) {
        float2 c  = cs[base - p];
        float  xv = buf[base - p];
        buf[base - p] = fmaf(c.x, u, c.y * xv);
        u = fmaf(-c.y, u, c.x * xv);
    }
    if (g == 63) buf[2047 + (2047 >> 5)] = u;   // y[0] = u_n
    NAMED_BAR(r + 1);

    // ---- Epilogue: coalesced float4 store, y[j] = buf[addr((j-1) mod N)] ----
    float* yr = y + row * (long)Nn;
    for (int j = h*1024 + lane*4; j < (h+1)*1024; j += 128) {
        float4 v;
        int k0 = (j + Nn - 1) & (Nn - 1);
        v.x = buf[k0 + (k0 >> 5)];
        v.y = buf[j     + (j     >> 5)];
        v.z = buf[j + 1 + ((j+1) >> 5)];
        v.w = buf[j + 2 + ((j+2) >> 5)];
        *reinterpret_cast<float4*>(yr + j) = v;
    }
}

extern "C" void kernel_launch(void* const* d_in, const int* in_sizes, int n_in,
                              void* d_out, int out_size) {
    const float* x      = (const float*)d_in[0];
    const float* angles = (const float*)d_in[1];
    if (n_in >= 2 && in_sizes[0] == Nn && in_sizes[1] != Nn) {
        const float* t = x; x = angles; angles = t;
    }
    float* y = (float*)d_out;

    cs_kernel<<<(Nn + 255) / 256, 256>>>(angles);
    wseg_kernel<<<1, Nn/SEG>>>();

    cudaFuncSetAttribute(givens_kernel,
                         cudaFuncAttributeMaxDynamicSharedMemorySize, SMEM_BYTES);
    int rows = out_size / Nn;                 // B = 16384
    int grid = (rows + RPB - 1) / RPB;
    givens_kernel<<<grid, THREADS, SMEM_BYTES>>>(x, y, rows);
}